// round 1
// baseline (speedup 1.0000x reference)
#include <cuda_runtime.h>
#include <cstdint>

#define B_N 256
#define C_N 1000
#define S_N 4
#define D_N 512
#define WROWS (C_N * S_N)   // 4000

// Scratch (no allocations allowed — device globals)
__device__ float g_xn[B_N * D_N];        // normalized x, 512 KB
__device__ float g_G[C_N * 16];          // normalized Gram per class, 64 KB
__device__ float g_invn[C_N * S_N];      // 1/max(||W[c,s]||, eps), 16 KB

__device__ __forceinline__ float dot4(float4 a, float4 b) {
    return a.x * b.x + a.y * b.y + a.z * b.z + a.w * b.w;
}

// packed fp32x2 FMA: d = a*b + d (lane-wise on 2 floats)
#define FFMA2(d, a, b) \
    asm("fma.rn.f32x2 %0, %1, %2, %0;" : "+l"(d) : "l"(a), "l"(b))

// ---------------------------------------------------------------------------
// Kernel A: xn = x / max(||x||, eps), one block per row, 128 threads (float4)
// ---------------------------------------------------------------------------
__global__ void norm_x_kernel(const float* __restrict__ x) {
    int row = blockIdx.x;
    int tid = threadIdx.x;  // 0..127
    const float4* xr = reinterpret_cast<const float4*>(x + row * D_N);
    float4 v = xr[tid];
    float ss = dot4(v, v);
    #pragma unroll
    for (int o = 16; o > 0; o >>= 1) ss += __shfl_xor_sync(0xffffffffu, ss, o);
    __shared__ float ws[4];
    if ((tid & 31) == 0) ws[tid >> 5] = ss;
    __syncthreads();
    float tot = ws[0] + ws[1] + ws[2] + ws[3];
    float inv = 1.0f / fmaxf(sqrtf(tot), 1e-12f);
    v.x *= inv; v.y *= inv; v.z *= inv; v.w *= inv;
    reinterpret_cast<float4*>(g_xn + row * D_N)[tid] = v;
}

// ---------------------------------------------------------------------------
// Kernel B: per class c compute raw Gram of W[c] (4x512), derive inv-norms and
// normalized Gram. One block per c, 128 threads (one float4 per row each).
// ---------------------------------------------------------------------------
__global__ void gram_kernel(const float* __restrict__ W) {
    int c = blockIdx.x;
    int tid = threadIdx.x;  // 0..127
    const float4* wr = reinterpret_cast<const float4*>(W + (size_t)c * S_N * D_N);
    float4 a = wr[tid];
    float4 b = wr[128 + tid];
    float4 e = wr[256 + tid];
    float4 d = wr[384 + tid];
    float p[10];
    p[0] = dot4(a, a); p[1] = dot4(a, b); p[2] = dot4(a, e); p[3] = dot4(a, d);
    p[4] = dot4(b, b); p[5] = dot4(b, e); p[6] = dot4(b, d);
    p[7] = dot4(e, e); p[8] = dot4(e, d);
    p[9] = dot4(d, d);
    #pragma unroll
    for (int o = 16; o > 0; o >>= 1) {
        #pragma unroll
        for (int i = 0; i < 10; i++) p[i] += __shfl_xor_sync(0xffffffffu, p[i], o);
    }
    __shared__ float red[4][10];
    if ((tid & 31) == 0) {
        #pragma unroll
        for (int i = 0; i < 10; i++) red[tid >> 5][i] = p[i];
    }
    __syncthreads();
    if (tid == 0) {
        float q[10];
        #pragma unroll
        for (int i = 0; i < 10; i++)
            q[i] = red[0][i] + red[1][i] + red[2][i] + red[3][i];
        // diag indices: (0,0)=0 (1,1)=4 (2,2)=7 (3,3)=9
        float inv[4];
        inv[0] = 1.0f / fmaxf(sqrtf(q[0]), 1e-12f);
        inv[1] = 1.0f / fmaxf(sqrtf(q[4]), 1e-12f);
        inv[2] = 1.0f / fmaxf(sqrtf(q[7]), 1e-12f);
        inv[3] = 1.0f / fmaxf(sqrtf(q[9]), 1e-12f);
        #pragma unroll
        for (int s = 0; s < 4; s++) g_invn[c * 4 + s] = inv[s];
        // pair index for (s,t) with s<=t
        const int pidx[4][4] = {
            {0, 1, 2, 3},
            {1, 4, 5, 6},
            {2, 5, 7, 8},
            {3, 6, 8, 9}};
        float* Gp = g_G + c * 16;
        #pragma unroll
        for (int s = 0; s < 4; s++)
            #pragma unroll
            for (int t = 0; t < 4; t++)
                Gp[s * 4 + t] = q[pidx[s][t]] * inv[s] * inv[t];
    }
}

// ---------------------------------------------------------------------------
// Kernel C: fused GEMM (L = xn * W^T) + per-(b,c) epilogue.
// Tile: 64 b-rows x 64 w-rows (=16 classes). K chunk = 64 (16 k-quads).
// Smem layout: [k-quad][row] as float4 holding (k..k+3); XOR-swizzled with the
// k-quad index to avoid 16-way STS bank conflicts.
// Thread (cx, by4): owns class c0+cx and b-rows b0+4*by4..+3 -> 16 accumulators
// (4 b x 4 s of ONE class), epilogue fully register-local.
// ---------------------------------------------------------------------------
__global__ __launch_bounds__(256, 2)
void adaproj_main_kernel(const float* __restrict__ W, float* __restrict__ out) {
    __shared__ float4 xAs[16][64];  // 16 KB
    __shared__ float4 wBs[16][64];  // 16 KB

    const int tid  = threadIdx.x;
    const int cx   = tid & 15;       // class within tile
    const int by4  = tid >> 4;       // 0..15 -> b quad
    const int c0   = blockIdx.x * 16;
    const int b0   = blockIdx.y * 64;
    // loader roles
    const int k4   = tid & 15;       // which k-quad
    const int rrow = tid >> 4;       // row base (0..15), +16*i

    unsigned long long acc[4][4];
    #pragma unroll
    for (int i = 0; i < 4; i++)
        #pragma unroll
        for (int j = 0; j < 4; j++) acc[i][j] = 0ull;

    for (int kc = 0; kc < D_N; kc += 64) {
        __syncthreads();
        // --- load xn chunk: rows b0..b0+63, cols kc..kc+63 ---
        #pragma unroll
        for (int i = 0; i < 4; i++) {
            int b = rrow + 16 * i;
            float4 v = *reinterpret_cast<const float4*>(
                g_xn + (size_t)(b0 + b) * D_N + kc + k4 * 4);
            xAs[k4][b ^ k4] = v;
        }
        // --- load W chunk: wrows c0*4..c0*4+63 (s-major permuted in smem) ---
        #pragma unroll
        for (int i = 0; i < 4; i++) {
            int wl = rrow + 16 * i;
            int gw = c0 * 4 + wl;
            float4 v = make_float4(0.f, 0.f, 0.f, 0.f);
            if (gw < WROWS)
                v = *reinterpret_cast<const float4*>(
                    W + (size_t)gw * D_N + kc + k4 * 4);
            int p = ((wl & 3) << 4) | (wl >> 2);  // s-major position
            wBs[k4][p ^ k4] = v;
        }
        __syncthreads();
        // --- compute: 16 k-quads ---
        #pragma unroll
        for (int kk = 0; kk < 16; kk++) {
            ulonglong2 a2[4], b2[4];
            #pragma unroll
            for (int i = 0; i < 4; i++)
                a2[i] = *reinterpret_cast<ulonglong2*>(&xAs[kk][(by4 * 4 + i) ^ kk]);
            #pragma unroll
            for (int j = 0; j < 4; j++)
                b2[j] = *reinterpret_cast<ulonglong2*>(&wBs[kk][((j << 4) | cx) ^ kk]);
            #pragma unroll
            for (int i = 0; i < 4; i++)
                #pragma unroll
                for (int j = 0; j < 4; j++) {
                    FFMA2(acc[i][j], a2[i].x, b2[j].x);
                    FFMA2(acc[i][j], a2[i].y, b2[j].y);
                }
        }
    }

    // --- epilogue: out[b,c] = (sum_s l_s^2) / max(sqrt(l^T G l), eps) ---
    const int c = c0 + cx;
    if (c < C_N) {
        float Gm[16], inv[4];
        const float* Gp = g_G + c * 16;
        #pragma unroll
        for (int t = 0; t < 16; t++) Gm[t] = Gp[t];
        #pragma unroll
        for (int s = 0; s < 4; s++) inv[s] = g_invn[c * 4 + s];
        #pragma unroll
        for (int i = 0; i < 4; i++) {
            float l[4];
            #pragma unroll
            for (int j = 0; j < 4; j++) {
                float lo = __uint_as_float((unsigned)(acc[i][j] & 0xffffffffull));
                float hi = __uint_as_float((unsigned)(acc[i][j] >> 32));
                l[j] = (lo + hi) * inv[j];
            }
            float num = l[0] * l[0] + l[1] * l[1] + l[2] * l[2] + l[3] * l[3];
            float den2 = 0.f;
            #pragma unroll
            for (int s = 0; s < 4; s++)
                #pragma unroll
                for (int t = 0; t < 4; t++)
                    den2 += l[s] * l[t] * Gm[s * 4 + t];
            float den = fmaxf(sqrtf(fmaxf(den2, 0.f)), 1e-12f);
            out[(size_t)(b0 + by4 * 4 + i) * C_N + c] = num / den;
        }
    }
}

// ---------------------------------------------------------------------------
extern "C" void kernel_launch(void* const* d_in, const int* in_sizes, int n_in,
                              void* d_out, int out_size) {
    const float* x = (const float*)d_in[0];   // [256, 512]
    const float* W = (const float*)d_in[1];   // [1000, 4, 512]
    float* out = (float*)d_out;               // [256, 1000]

    norm_x_kernel<<<B_N, 128>>>(x);
    gram_kernel<<<C_N, 128>>>(W);
    dim3 grid((WROWS + 63) / 64, B_N / 64);   // (63, 4)
    adaproj_main_kernel<<<grid, 256>>>(W, out);
}

// round 5
// speedup vs baseline: 2.0838x; 2.0838x over previous
#include <cuda_runtime.h>
#include <cstdint>

#define B_N   256
#define C_N   1000
#define D_N   512
#define WROWS 4000

// ---------------- device scratch (no allocations allowed) ----------------
__device__ float g_xn[B_N * D_N];      // tf32-rounded normalized x   (512 KB)
__device__ float g_Wt[WROWS * D_N];    // tf32-rounded W              (8 MB)
__device__ float g_G[C_N * 16];        // normalized Gram per class   (64 KB)
__device__ float g_invn[C_N * 4];      // 1/max(||W[c,s]||,eps)       (16 KB)

// ---------------- helpers ----------------
__device__ __forceinline__ float dot4(float4 a, float4 b) {
    return a.x * b.x + a.y * b.y + a.z * b.z + a.w * b.w;
}
__device__ __forceinline__ float tf32r(float v) {
    unsigned r;
    asm("cvt.rna.tf32.f32 %0, %1;" : "=r"(r) : "f"(v));
    return __uint_as_float(r);
}
__device__ __forceinline__ float4 tf32r4(float4 v) {
    return make_float4(tf32r(v.x), tf32r(v.y), tf32r(v.z), tf32r(v.w));
}
__device__ __forceinline__ uint32_t smem_u32(const void* p) {
    uint32_t a;
    asm("{ .reg .u64 t; cvta.to.shared.u64 t, %1; cvt.u32.u64 %0, t; }" : "=r"(a) : "l"(p));
    return a;
}
__device__ __forceinline__ void cp16(uint32_t dst, const void* src) {
    asm volatile("cp.async.cg.shared.global [%0], [%1], 16;" :: "r"(dst), "l"(src));
}
__device__ __forceinline__ void mma_tf32(float* d, const uint32_t* a, const uint32_t* b) {
    asm volatile(
        "mma.sync.aligned.m16n8k8.row.col.f32.tf32.tf32.f32 "
        "{%0,%1,%2,%3}, {%4,%5,%6,%7}, {%8,%9}, {%0,%1,%2,%3};"
        : "+f"(d[0]), "+f"(d[1]), "+f"(d[2]), "+f"(d[3])
        : "r"(a[0]), "r"(a[1]), "r"(a[2]), "r"(a[3]), "r"(b[0]), "r"(b[1]));
}

// ---------------------------------------------------------------------------
// Prep kernel: blocks [0,256) normalize x -> g_xn (tf32-rounded);
//              blocks [256,1256) per-class Gram + invnorm + tf32 W copy.
// ---------------------------------------------------------------------------
__global__ __launch_bounds__(128) void prep_kernel(const float* __restrict__ x,
                                                   const float* __restrict__ W) {
    const int tid = threadIdx.x;
    if (blockIdx.x < 256) {
        const int row = blockIdx.x;
        const float4* xr = reinterpret_cast<const float4*>(x + (size_t)row * D_N);
        float4 v = xr[tid];
        float ss = dot4(v, v);
        #pragma unroll
        for (int o = 16; o > 0; o >>= 1) ss += __shfl_xor_sync(0xffffffffu, ss, o);
        __shared__ float ws[4];
        if ((tid & 31) == 0) ws[tid >> 5] = ss;
        __syncthreads();
        float inv = 1.0f / fmaxf(sqrtf(ws[0] + ws[1] + ws[2] + ws[3]), 1e-12f);
        v.x *= inv; v.y *= inv; v.z *= inv; v.w *= inv;
        reinterpret_cast<float4*>(g_xn + (size_t)row * D_N)[tid] = tf32r4(v);
    } else {
        const int c = blockIdx.x - 256;
        const float4* wr = reinterpret_cast<const float4*>(W + (size_t)c * 4 * D_N);
        float4* wt = reinterpret_cast<float4*>(g_Wt + (size_t)c * 4 * D_N);
        float4 a = wr[tid], b = wr[128 + tid], e = wr[256 + tid], d = wr[384 + tid];
        wt[tid] = tf32r4(a); wt[128 + tid] = tf32r4(b);
        wt[256 + tid] = tf32r4(e); wt[384 + tid] = tf32r4(d);
        float p[10];
        p[0]=dot4(a,a); p[1]=dot4(a,b); p[2]=dot4(a,e); p[3]=dot4(a,d);
        p[4]=dot4(b,b); p[5]=dot4(b,e); p[6]=dot4(b,d);
        p[7]=dot4(e,e); p[8]=dot4(e,d); p[9]=dot4(d,d);
        #pragma unroll
        for (int o = 16; o > 0; o >>= 1)
            #pragma unroll
            for (int i = 0; i < 10; i++) p[i] += __shfl_xor_sync(0xffffffffu, p[i], o);
        __shared__ float red[4][10];
        if ((tid & 31) == 0)
            #pragma unroll
            for (int i = 0; i < 10; i++) red[tid >> 5][i] = p[i];
        __syncthreads();
        if (tid == 0) {
            float q[10];
            #pragma unroll
            for (int i = 0; i < 10; i++) q[i] = red[0][i]+red[1][i]+red[2][i]+red[3][i];
            float inv[4];
            inv[0] = 1.0f / fmaxf(sqrtf(q[0]), 1e-12f);
            inv[1] = 1.0f / fmaxf(sqrtf(q[4]), 1e-12f);
            inv[2] = 1.0f / fmaxf(sqrtf(q[7]), 1e-12f);
            inv[3] = 1.0f / fmaxf(sqrtf(q[9]), 1e-12f);
            #pragma unroll
            for (int s = 0; s < 4; s++) g_invn[c * 4 + s] = inv[s];
            const int pidx[4][4] = {{0,1,2,3},{1,4,5,6},{2,5,7,8},{3,6,8,9}};
            float* Gp = g_G + c * 16;
            #pragma unroll
            for (int s = 0; s < 4; s++)
                #pragma unroll
                for (int t = 0; t < 4; t++)
                    Gp[s * 4 + t] = q[pidx[s][t]] * inv[s] * inv[t];
        }
    }
}

// ---------------------------------------------------------------------------
// GEMM (mma.sync tf32) + fused epilogue.
// CTA tile: M=64 wrows (16 classes) x N=128 b. Warp tile 32x32, warpgrid 2x4.
// K in 16 chunks of 32, double-buffered cp.async. Smem rows pitch 36 floats
// (conflict-free fragment loads, 16B-aligned cp.async stores).
// ---------------------------------------------------------------------------
#define KP       36                  // smem pitch (floats) for 32-float K chunk
#define STG_F    ((64 + 128) * KP)   // floats per stage = 6912
#define SMEM_F   (2 * STG_F)         // 13824 floats = 55296 B
#define CP       133                 // C-tile pitch: odd -> scalar stores only!

__global__ __launch_bounds__(256, 1) void gemm_epi_kernel(float* __restrict__ out) {
    extern __shared__ float sm[];
    const int tid  = threadIdx.x;
    const int wid  = tid >> 5, lane = tid & 31;
    const int g    = lane >> 2, tig = lane & 3;
    const int m_off = (wid & 1) * 32;        // warpgrid 2 (M) x 4 (N)
    const int n_off = (wid >> 1) * 32;
    const int w0 = blockIdx.x * 64;          // wrow base (16 classes)
    const int b0 = blockIdx.y * 128;

    float acc[2][4][4];
    #pragma unroll
    for (int mi = 0; mi < 2; mi++)
        #pragma unroll
        for (int nj = 0; nj < 4; nj++)
            #pragma unroll
            for (int q = 0; q < 4; q++) acc[mi][nj][q] = 0.f;

    const uint32_t sbase = smem_u32(sm);
    auto loadchunk = [&](int ch, int buf) {
        const uint32_t Ab = sbase + buf * (STG_F * 4);
        const uint32_t Bb = Ab + 64 * KP * 4;
        const int kc = ch * 32;
        #pragma unroll
        for (int i = 0; i < 2; i++) {               // A: 64 rows x 8 chunks
            int e = tid + 256 * i;
            int r = e >> 3, c16 = e & 7;
            int ar = w0 + r; if (ar > WROWS - 1) ar = WROWS - 1;
            cp16(Ab + (r * KP + c16 * 4) * 4, g_Wt + (size_t)ar * D_N + kc + c16 * 4);
        }
        #pragma unroll
        for (int i = 0; i < 4; i++) {               // B: 128 rows x 8 chunks
            int e = tid + 256 * i;
            int r = e >> 3, c16 = e & 7;
            cp16(Bb + (r * KP + c16 * 4) * 4, g_xn + (size_t)(b0 + r) * D_N + kc + c16 * 4);
        }
        asm volatile("cp.async.commit_group;" ::: "memory");
    };

    loadchunk(0, 0);
    for (int ch = 0; ch < 16; ch++) {
        if (ch + 1 < 16) {
            loadchunk(ch + 1, (ch + 1) & 1);
            asm volatile("cp.async.wait_group 1;" ::: "memory");
        } else {
            asm volatile("cp.async.wait_group 0;" ::: "memory");
        }
        __syncthreads();
        const float* As = sm + (ch & 1) * STG_F;
        const float* Bs = As + 64 * KP;
        #pragma unroll
        for (int k8 = 0; k8 < 4; k8++) {
            uint32_t af[2][4], bf[4][2];
            #pragma unroll
            for (int mi = 0; mi < 2; mi++) {
                int r = m_off + 16 * mi + g;
                af[mi][0] = __float_as_uint(As[r * KP + k8 * 8 + tig]);
                af[mi][1] = __float_as_uint(As[(r + 8) * KP + k8 * 8 + tig]);
                af[mi][2] = __float_as_uint(As[r * KP + k8 * 8 + tig + 4]);
                af[mi][3] = __float_as_uint(As[(r + 8) * KP + k8 * 8 + tig + 4]);
            }
            #pragma unroll
            for (int nj = 0; nj < 4; nj++) {
                int r = n_off + 8 * nj + g;
                bf[nj][0] = __float_as_uint(Bs[r * KP + k8 * 8 + tig]);
                bf[nj][1] = __float_as_uint(Bs[r * KP + k8 * 8 + tig + 4]);
            }
            #pragma unroll
            for (int mi = 0; mi < 2; mi++)
                #pragma unroll
                for (int nj = 0; nj < 4; nj++)
                    mma_tf32(acc[mi][nj], af[mi], bf[nj]);
        }
        __syncthreads();
    }

    // ---- dump C tile (64 x 128) to smem; SCALAR stores (odd pitch) ----
    float* Cs = sm;  // 64*133 = 8512 floats, fits in stage memory
    #pragma unroll
    for (int mi = 0; mi < 2; mi++)
        #pragma unroll
        for (int nj = 0; nj < 4; nj++) {
            int r = m_off + 16 * mi + g;
            int cl = n_off + 8 * nj + 2 * tig;
            Cs[r * CP + cl]           = acc[mi][nj][0];
            Cs[r * CP + cl + 1]       = acc[mi][nj][1];
            Cs[(r + 8) * CP + cl]     = acc[mi][nj][2];
            Cs[(r + 8) * CP + cl + 1] = acc[mi][nj][3];
        }
    __syncthreads();

    // ---- fused epilogue: out[b, c] = (sum_s l^2) / max(sqrt(l^T G l), eps) ----
    const int cc = tid & 15;                 // class within tile
    const int bb = tid >> 4;                 // b sub-index
    const int cg = blockIdx.x * 16 + cc;
    if (cg < C_N) {
        float inv[4], Gm[16];
        #pragma unroll
        for (int s = 0; s < 4; s++) inv[s] = g_invn[cg * 4 + s];
        #pragma unroll
        for (int t = 0; t < 16; t++) Gm[t] = g_G[cg * 16 + t];
        #pragma unroll
        for (int i = 0; i < 8; i++) {
            int b = bb + 16 * i;
            float l[4];
            #pragma unroll
            for (int s = 0; s < 4; s++)
                l[s] = Cs[(4 * cc + s) * CP + b] * inv[s];
            float num = l[0]*l[0] + l[1]*l[1] + l[2]*l[2] + l[3]*l[3];
            float den2 = 0.f;
            #pragma unroll
            for (int s = 0; s < 4; s++)
                #pragma unroll
                for (int t = 0; t < 4; t++)
                    den2 += l[s] * l[t] * Gm[s * 4 + t];
            out[(size_t)(b0 + b) * C_N + cg] =
                num / fmaxf(sqrtf(fmaxf(den2, 0.f)), 1e-12f);
        }
    }
}

// ---------------------------------------------------------------------------
extern "C" void kernel_launch(void* const* d_in, const int* in_sizes, int n_in,
                              void* d_out, int out_size) {
    const float* x = (const float*)d_in[0];   // [256, 512]
    const float* W = (const float*)d_in[1];   // [1000, 4, 512]
    float* out = (float*)d_out;               // [256, 1000]

    cudaFuncSetAttribute(gemm_epi_kernel,
                         cudaFuncAttributeMaxDynamicSharedMemorySize, SMEM_F * 4);
    prep_kernel<<<1256, 128>>>(x, W);
    gemm_epi_kernel<<<dim3(63, 2), 256, SMEM_F * 4>>>(out);
}

// round 8
// speedup vs baseline: 2.3408x; 1.1233x over previous
#include <cuda_runtime.h>
#include <cstdint>

#define B_N   256
#define C_N   1000
#define D_N   512
#define WROWS 4000
#define RG_MAX 249              // last valid 16-row group (250 groups)

// ---------------- device scratch (no allocations allowed) ----------------
// Packed fragment-order operands (written by prep, streamed by GEMM):
// g_Wp[((r16*16 + ch)*4 + k8)*32 + lane] : float4 = {W[R+g][K+t], W[R+8+g][K+t],
//        W[R+g][K+t+4], W[R+8+g][K+t+4]},  R=16*r16, K=32ch+8k8, lane=(g<<2)|t
// g_xp (float2 view of g_xp4)[((n8*16 + ch)*4 + k8)*32 + lane] :
//        float2 = {xn[8*n8+g][K+t], xn[8*n8+g][K+t+4]}
__device__ float4 g_Wp[250 * 16 * 4 * 32];   // 8 MB
__device__ float4 g_xp4[32 * 16 * 4 * 16];   // 512 KB (float2 pairs in float4)
__device__ float  g_G[C_N * 16];
__device__ float  g_invn[C_N * 4];

// ---------------- helpers ----------------
__device__ __forceinline__ float dot4(float4 a, float4 b) {
    return a.x * b.x + a.y * b.y + a.z * b.z + a.w * b.w;
}
__device__ __forceinline__ float tf32r(float v) {
    unsigned r;
    asm("cvt.rna.tf32.f32 %0, %1;" : "=r"(r) : "f"(v));
    return __uint_as_float(r);
}
__device__ __forceinline__ float4 tf32r4(float4 v) {
    return make_float4(tf32r(v.x), tf32r(v.y), tf32r(v.z), tf32r(v.w));
}
__device__ __forceinline__ uint32_t smem_u32(const void* p) {
    uint32_t a;
    asm("{ .reg .u64 t; cvta.to.shared.u64 t, %1; cvt.u32.u64 %0, t; }" : "=r"(a) : "l"(p));
    return a;
}
__device__ __forceinline__ void cp16(uint32_t dst, const void* src) {
    asm volatile("cp.async.cg.shared.global [%0], [%1], 16;" :: "r"(dst), "l"(src));
}
__device__ __forceinline__ void mma_tf32(float* d, const uint32_t* a, const uint32_t* b) {
    asm volatile(
        "mma.sync.aligned.m16n8k8.row.col.f32.tf32.tf32.f32 "
        "{%0,%1,%2,%3}, {%4,%5,%6,%7}, {%8,%9}, {%0,%1,%2,%3};"
        : "+f"(d[0]), "+f"(d[1]), "+f"(d[2]), "+f"(d[3])
        : "r"(a[0]), "r"(a[1]), "r"(a[2]), "r"(a[3]), "r"(b[0]), "r"(b[1]));
}

// ---------------------------------------------------------------------------
// Prep: blocks [0,32): normalize 8 x-rows, pack to g_xp.
//       blocks [32,282): 16 W-rows (4 classes): Gram+invnorm (raw fp32),
//       tf32-round + pack to g_Wp.
// ---------------------------------------------------------------------------
__global__ __launch_bounds__(256) void prep_kernel(const float* __restrict__ x,
                                                   const float* __restrict__ W) {
    __shared__ float tile[16][516];
    const int tid = threadIdx.x, lane = tid & 31, w = tid >> 5;

    if (blockIdx.x < 32) {
        const int n8 = blockIdx.x;          // 8-row group of x
        const int row = n8 * 8 + w;         // warp w: one row (w always < 8)
        {
            const float4* xr = reinterpret_cast<const float4*>(x + (size_t)row * D_N);
            float4 v[4]; float ss = 0.f;
            #pragma unroll
            for (int i = 0; i < 4; i++) { v[i] = xr[lane + 32 * i]; ss += dot4(v[i], v[i]); }
            #pragma unroll
            for (int o = 16; o > 0; o >>= 1) ss += __shfl_xor_sync(0xffffffffu, ss, o);
            float inv = 1.0f / fmaxf(sqrtf(ss), 1e-12f);
            #pragma unroll
            for (int i = 0; i < 4; i++) {
                float4 s = tf32r4(make_float4(v[i].x*inv, v[i].y*inv, v[i].z*inv, v[i].w*inv));
                int col = 4 * lane + 128 * i;
                tile[w][col] = s.x; tile[w][col+1] = s.y;
                tile[w][col+2] = s.z; tile[w][col+3] = s.w;
            }
        }
        __syncthreads();
        float2* xp = reinterpret_cast<float2*>(g_xp4);
        #pragma unroll
        for (int j = 0; j < 8; j++) {
            int idx = j * 256 + tid;                  // 2048 float2
            int ch = idx >> 7, k8 = (idx >> 5) & 3, l = idx & 31;
            int g = l >> 2, t = l & 3;
            int col = ch * 32 + k8 * 8 + t;
            xp[((n8 * 16 + ch) * 4 + k8) * 32 + l] =
                make_float2(tile[g][col], tile[g][col + 4]);
        }
    } else {
        const int r16 = blockIdx.x - 32;            // 16-wrow group = 4 classes
        const int wr0 = r16 * 16;
        // stage tf32-rounded rows to smem (coalesced float4)
        const float4* W4 = reinterpret_cast<const float4*>(W);
        #pragma unroll
        for (int j = 0; j < 8; j++) {
            int idx = j * 256 + tid;                 // 2048 float4
            int r = idx >> 7, q = idx & 127;
            float4 v = tf32r4(W4[(size_t)(wr0 + r) * 128 + q]);
            *reinterpret_cast<float4*>(&tile[r][q * 4]) = v;
        }
        __syncthreads();
        // Gram from RAW W: warp w<4 handles class c = 4*r16 + w
        if (w < 4) {
            const int c = 4 * r16 + w;
            const float4* wr = reinterpret_cast<const float4*>(W + (size_t)c * 4 * D_N);
            float4 ra[4][4];
            #pragma unroll
            for (int r = 0; r < 4; r++)
                #pragma unroll
                for (int i = 0; i < 4; i++)
                    ra[r][i] = wr[r * 128 + lane * 4 + i];
            float p[10];
            #pragma unroll
            for (int i = 0; i < 10; i++) p[i] = 0.f;
            #pragma unroll
            for (int i = 0; i < 4; i++) {
                p[0] += dot4(ra[0][i], ra[0][i]); p[1] += dot4(ra[0][i], ra[1][i]);
                p[2] += dot4(ra[0][i], ra[2][i]); p[3] += dot4(ra[0][i], ra[3][i]);
                p[4] += dot4(ra[1][i], ra[1][i]); p[5] += dot4(ra[1][i], ra[2][i]);
                p[6] += dot4(ra[1][i], ra[3][i]); p[7] += dot4(ra[2][i], ra[2][i]);
                p[8] += dot4(ra[2][i], ra[3][i]); p[9] += dot4(ra[3][i], ra[3][i]);
            }
            #pragma unroll
            for (int o = 16; o > 0; o >>= 1)
                #pragma unroll
                for (int i = 0; i < 10; i++) p[i] += __shfl_xor_sync(0xffffffffu, p[i], o);
            if (lane == 0) {
                float inv[4];
                inv[0] = 1.0f / fmaxf(sqrtf(p[0]), 1e-12f);
                inv[1] = 1.0f / fmaxf(sqrtf(p[4]), 1e-12f);
                inv[2] = 1.0f / fmaxf(sqrtf(p[7]), 1e-12f);
                inv[3] = 1.0f / fmaxf(sqrtf(p[9]), 1e-12f);
                #pragma unroll
                for (int s = 0; s < 4; s++) g_invn[c * 4 + s] = inv[s];
                const int pidx[4][4] = {{0,1,2,3},{1,4,5,6},{2,5,7,8},{3,6,8,9}};
                #pragma unroll
                for (int s = 0; s < 4; s++)
                    #pragma unroll
                    for (int t = 0; t < 4; t++)
                        g_G[c * 16 + s * 4 + t] = p[pidx[s][t]] * inv[s] * inv[t];
            }
        }
        // pack A fragments
        #pragma unroll
        for (int j = 0; j < 8; j++) {
            int idx = j * 256 + tid;                 // 2048 float4
            int ch = idx >> 7, k8 = (idx >> 5) & 3, l = idx & 31;
            int g = l >> 2, t = l & 3;
            int col = ch * 32 + k8 * 8 + t;
            g_Wp[((r16 * 16 + ch) * 4 + k8) * 32 + l] =
                make_float4(tile[g][col], tile[g + 8][col],
                            tile[g][col + 4], tile[g + 8][col + 4]);
        }
    }
}

// ---------------------------------------------------------------------------
// GEMM: 64 wrows x 64 b per CTA, 128 threads (4 warps, warpgrid 2x2, warp
// tile 32x32). 3-stage cp.async pipeline, packed-fragment smem (A: LDS.128,
// B: LDS.64, conflict-free). Fused Gram epilogue.
// ---------------------------------------------------------------------------
#define STG_F  4096                 // floats per stage (A 2048 + B 2048) = 16 KB
#define CP     67                   // C-tile pitch (odd -> scalar stores only)

__global__ __launch_bounds__(128, 2) void gemm_epi_kernel(float* __restrict__ out) {
    extern __shared__ float sm[];
    const int tid = threadIdx.x, wid = tid >> 5, lane = tid & 31;
    const int m_sel = wid & 1, n_sel = wid >> 1;
    const int rg0 = blockIdx.x * 4;       // 16-row groups
    const int ng0 = blockIdx.y * 8;       // 8-col groups
    const int b0 = blockIdx.y * 64;

    float acc[2][4][4];
    #pragma unroll
    for (int mi = 0; mi < 2; mi++)
        #pragma unroll
        for (int nj = 0; nj < 4; nj++)
            #pragma unroll
            for (int q = 0; q < 4; q++) acc[mi][nj][q] = 0.f;

    const uint32_t sbase = smem_u32(sm);
    const float2* xp = reinterpret_cast<const float2*>(g_xp4);

    auto load = [&](int ch, int st) {
        const uint32_t Ab = sbase + st * (STG_F * 4);
        const uint32_t Bb = Ab + 2048 * 4;
        #pragma unroll
        for (int i = 0; i < 4; i++) {                 // A: 512 float4
            int f = i * 128 + tid;
            int grp = f >> 7, k8 = (f >> 5) & 3, l = f & 31;
            int gg = rg0 + grp; if (gg > RG_MAX) gg = RG_MAX;
            cp16(Ab + f * 16, g_Wp + ((gg * 16 + ch) * 4 + k8) * 32 + l);
        }
        #pragma unroll
        for (int i = 0; i < 4; i++) {                 // B: 512 x 16B (1024 float2)
            int f = i * 128 + tid;
            int grp = f >> 6, k8 = (f >> 4) & 3, lp = (f & 15) * 2;
            cp16(Bb + f * 16, xp + (((ng0 + grp) * 16 + ch) * 4 + k8) * 32 + lp);
        }
        asm volatile("cp.async.commit_group;" ::: "memory");
    };

    load(0, 0);
    load(1, 1);
    #pragma unroll
    for (int ch = 0; ch < 16; ch++) {
        if (ch < 15) asm volatile("cp.async.wait_group 1;" ::: "memory");
        else         asm volatile("cp.async.wait_group 0;" ::: "memory");
        __syncthreads();
        if (ch + 2 < 16) load(ch + 2, (ch + 2) % 3);
        const float* As = sm + (ch % 3) * STG_F;
        const float* Bs = As + 2048;
        #pragma unroll
        for (int k8 = 0; k8 < 4; k8++) {
            float4 afv[2]; float2 bfv[4];
            #pragma unroll
            for (int mi = 0; mi < 2; mi++) {
                int grp = m_sel * 2 + mi;
                afv[mi] = *reinterpret_cast<const float4*>(
                    As + ((grp * 4 + k8) * 32 + lane) * 4);
            }
            #pragma unroll
            for (int nj = 0; nj < 4; nj++) {
                int grp = n_sel * 4 + nj;
                bfv[nj] = *reinterpret_cast<const float2*>(
                    Bs + ((grp * 4 + k8) * 32 + lane) * 2);
            }
            #pragma unroll
            for (int mi = 0; mi < 2; mi++)
                #pragma unroll
                for (int nj = 0; nj < 4; nj++)
                    mma_tf32(acc[mi][nj],
                             reinterpret_cast<const uint32_t*>(&afv[mi]),
                             reinterpret_cast<const uint32_t*>(&bfv[nj]));
        }
    }
    __syncthreads();

    // ---- C dump (64 x 64, scalar stores, odd pitch) ----
    float* Cs = sm;
    {
        const int g = lane >> 2, t = lane & 3;
        #pragma unroll
        for (int mi = 0; mi < 2; mi++)
            #pragma unroll
            for (int nj = 0; nj < 4; nj++) {
                int r = m_sel * 32 + 16 * mi + g;
                int c = n_sel * 32 + 8 * nj + 2 * t;
                Cs[r * CP + c]           = acc[mi][nj][0];
                Cs[r * CP + c + 1]       = acc[mi][nj][1];
                Cs[(r + 8) * CP + c]     = acc[mi][nj][2];
                Cs[(r + 8) * CP + c + 1] = acc[mi][nj][3];
            }
    }
    __syncthreads();

    // ---- fused epilogue ----
    const int cc = tid & 15, bb = tid >> 4;       // 16 classes x 8 b-threads
    const int cg = blockIdx.x * 16 + cc;
    if (cg < C_N) {
        float inv[4], Gm[16];
        #pragma unroll
        for (int s = 0; s < 4; s++) inv[s] = g_invn[cg * 4 + s];
        #pragma unroll
        for (int t = 0; t < 16; t++) Gm[t] = g_G[cg * 16 + t];
        #pragma unroll
        for (int i = 0; i < 8; i++) {
            int b = bb + 8 * i;
            float l[4];
            #pragma unroll
            for (int s = 0; s < 4; s++)
                l[s] = Cs[(4 * cc + s) * CP + b] * inv[s];
            float num = l[0]*l[0] + l[1]*l[1] + l[2]*l[2] + l[3]*l[3];
            float den2 = 0.f;
            #pragma unroll
            for (int s = 0; s < 4; s++)
                #pragma unroll
                for (int t = 0; t < 4; t++)
                    den2 += l[s] * l[t] * Gm[s * 4 + t];
            out[(size_t)(b0 + b) * C_N + cg] =
                num / fmaxf(sqrtf(fmaxf(den2, 0.f)), 1e-12f);
        }
    }
}

// ---------------------------------------------------------------------------
extern "C" void kernel_launch(void* const* d_in, const int* in_sizes, int n_in,
                              void* d_out, int out_size) {
    const float* x = (const float*)d_in[0];   // [256, 512]
    const float* W = (const float*)d_in[1];   // [1000, 4, 512]
    float* out = (float*)d_out;               // [256, 1000]

    cudaFuncSetAttribute(gemm_epi_kernel,
                         cudaFuncAttributeMaxDynamicSharedMemorySize, 3 * STG_F * 4);
    prep_kernel<<<282, 256>>>(x, W);
    gemm_epi_kernel<<<dim3(63, 4), 128, 3 * STG_F * 4>>>(out);
}